// round 9
// baseline (speedup 1.0000x reference)
#include <cuda_runtime.h>
#include <cuda_bf16.h>
#include <cstdint>

#define LSEQ 2048
#define NBH  16
#define NT   512
#define SCALE 0.07216878364870323f   // 1/sqrt(3*64)
#define SSTR 2052
#define KSTR 68                      // K chunk row stride (words)
#define VSTR2 132                    // V chunk row stride (words)

#define OFF_KV 131328                // sS = 16*2052*4
#define KBUF   34816                 // 128*68*4
#define VBUF   33792                 // 64*132*4
#define OFF_Q  200960                // OFF_KV + 2*KBUF
#define SMEM_BYTES 205312

__device__ uint32_t g_qp[(size_t)NBH * LSEQ * 64];
__device__ uint32_t g_kp[(size_t)NBH * LSEQ * 64];
__device__ uint32_t g_vp[(size_t)NBH * 64 * LSEQ];   // [bh][dim][j]

__device__ __forceinline__ uint32_t packsplit(float x) {
    __nv_bfloat16 h = __float2bfloat16(x);
    float hf = __bfloat162float(h);
    __nv_bfloat16 l = __float2bfloat16(x - hf);
    unsigned short hs = *(unsigned short*)&h, ls = *(unsigned short*)&l;
    return (uint32_t)hs | ((uint32_t)ls << 16);
}
__device__ __forceinline__ uint32_t smem_u32(const void* p) {
    uint32_t a;
    asm("{ .reg .u64 t; cvta.to.shared.u64 t, %1; cvt.u32.u64 %0, t; }" : "=r"(a) : "l"(p));
    return a;
}
#define PHI(w0,w1) __byte_perm((w0), (w1), 0x5410)
#define PLO(w0,w1) __byte_perm((w0), (w1), 0x7632)
#define MMA(c, a0,a1,a2,a3, b0,b1) \
  asm volatile("mma.sync.aligned.m16n8k16.row.col.f32.bf16.bf16.f32 " \
    "{%0,%1,%2,%3}, {%4,%5,%6,%7}, {%8,%9}, {%0,%1,%2,%3};" \
    : "+f"((c)[0]), "+f"((c)[1]), "+f"((c)[2]), "+f"((c)[3]) \
    : "r"(a0), "r"(a1), "r"(a2), "r"(a3), "r"(b0), "r"(b1))
#define CPA(dst, src) asm volatile("cp.async.cg.shared.global [%0], [%1], 16;" :: "r"(dst), "l"(src))
#define CPCOMMIT()    asm volatile("cp.async.commit_group;" ::: "memory")
#define CPWAIT0()     asm volatile("cp.async.wait_group 0;" ::: "memory")

// ---------------- prep: pack Q/K; transpose+pack V ----------------
__global__ void prep_kernel(const float* __restrict__ Q, const float* __restrict__ K,
                            const float* __restrict__ V)
{
    const int t = threadIdx.x;
    if (blockIdx.x < 1024) {
        #pragma unroll
        for (int i = 0; i < 2; i++) {
            size_t idx4 = (size_t)blockIdx.x * 512 + t + (size_t)i * 256;
            float4 q = ((const float4*)Q)[idx4];
            ((uint4*)g_qp)[idx4] = make_uint4(packsplit(q.x), packsplit(q.y),
                                             packsplit(q.z), packsplit(q.w));
            float4 k = ((const float4*)K)[idx4];
            ((uint4*)g_kp)[idx4] = make_uint4(packsplit(k.x), packsplit(k.y),
                                             packsplit(k.z), packsplit(k.w));
        }
    } else {
        __shared__ float sT[64 * 65];
        int bi = blockIdx.x - 1024, bh = bi >> 5, jt = bi & 31;
        const float* Vb = V + ((size_t)bh * LSEQ + jt * 64) * 64;
        #pragma unroll
        for (int i = 0; i < 4; i++) {
            int q = t + i * 256, j = q >> 4, n4 = (q & 15) * 4;
            float4 v = *(const float4*)(Vb + (size_t)j * 64 + n4);
            sT[(n4+0)*65 + j] = v.x; sT[(n4+1)*65 + j] = v.y;
            sT[(n4+2)*65 + j] = v.z; sT[(n4+3)*65 + j] = v.w;
        }
        __syncthreads();
        #pragma unroll
        for (int i = 0; i < 4; i++) {
            int q = t + i * 256, dim = q >> 4, j4 = (q & 15) * 4;
            uint4 pw = make_uint4(packsplit(sT[dim*65 + j4]),
                                  packsplit(sT[dim*65 + j4 + 1]),
                                  packsplit(sT[dim*65 + j4 + 2]),
                                  packsplit(sT[dim*65 + j4 + 3]));
            *(uint4*)(g_vp + ((size_t)bh * 64 + dim) * LSEQ + jt * 64 + j4) = pw;
        }
    }
}

__device__ __forceinline__ unsigned mget2(const unsigned char* M, int flag, size_t off)
{
    if (flag == 1) { int2 v = *(const int2*)((const int*)M + off);
        return (v.x?1u:0u) | (v.y?2u:0u); }
    if (flag == 0) { const unsigned char* p = M + off;
        return (p[0]?1u:0u) | (p[1]?2u:0u); }
    float2 v = *(const float2*)((const float*)M + off);
    return (v.x!=0.f?1u:0u) | (v.y!=0.f?2u:0u);
}

// ---------------- main fused kernel ----------------
__global__ __launch_bounds__(NT, 1)
void raa_kernel(const unsigned char* __restrict__ M,
                const float* __restrict__ TS, const float* __restrict__ LS,
                float* __restrict__ O, float* __restrict__ P)
{
    extern __shared__ char smem[];
    float*    sS  = (float*)smem;
    uint32_t* sSw = (uint32_t*)smem;
    uint32_t* sQ  = (uint32_t*)(smem + OFF_Q);
    __shared__ float sRow[16];
    __shared__ float sPart[16 * 16];
    __shared__ int   sFlag;

    const int t = threadIdx.x, w = t >> 5, lane = t & 31;
    const int g = lane >> 2, tig = lane & 3;
    const int bh = blockIdx.y, i0 = blockIdx.x * 16;

    if (t == 0) {
        const int* mi = (const int*)M; const float* mf = (const float*)M;
        bool okI = true, okF = true;
        for (int i = 0; i < 64; i++) {
            int vi = mi[i]; float vf = mf[i];
            if (vi != 0 && vi != 1)     okI = false;
            if (vf != 0.f && vf != 1.f) okF = false;
        }
        sFlag = okI ? 1 : (okF ? 2 : 0);
    }
    if (t < 256) {
        int row = t >> 4, k4 = (t & 15) * 4;
        uint4 pw = *((const uint4*)(g_qp + ((size_t)bh * LSEQ + i0) * 64) + t);
        *(uint4*)(sQ + row * KSTR + k4) = pw;
    }
    __syncthreads();
    const int flag = sFlag;

    // Q A-frags resident through phase 1
    uint32_t qh[16], ql[16];
    #pragma unroll
    for (int ks = 0; ks < 4; ks++) {
        int c0 = ks * 16 + 2 * tig;
        uint32_t w00 = sQ[g * KSTR + c0],           w01 = sQ[g * KSTR + c0 + 1];
        uint32_t w10 = sQ[(g + 8) * KSTR + c0],     w11 = sQ[(g + 8) * KSTR + c0 + 1];
        uint32_t w20 = sQ[g * KSTR + c0 + 8],       w21 = sQ[g * KSTR + c0 + 9];
        uint32_t w30 = sQ[(g + 8) * KSTR + c0 + 8], w31 = sQ[(g + 8) * KSTR + c0 + 9];
        qh[ks*4+0] = PHI(w00, w01); ql[ks*4+0] = PLO(w00, w01);
        qh[ks*4+1] = PHI(w10, w11); ql[ks*4+1] = PLO(w10, w11);
        qh[ks*4+2] = PHI(w20, w21); ql[ks*4+2] = PLO(w20, w21);
        qh[ks*4+3] = PHI(w30, w31); ql[ks*4+3] = PLO(w30, w31);
    }

    // ---- Phase 1: S = exp((Q K^T + bias) * scale) fused, cp.async double buffer ----
    const uint4* Kp = (const uint4*)(g_kp + (size_t)bh * LSEQ * 64);
    const uint32_t kbuf0 = smem_u32(smem + OFF_KV);
    {
        // issue chunk 0
        #pragma unroll
        for (int i = 0; i < 4; i++) {
            int idx = t + i * NT, j = idx >> 4, k4 = idx & 15;
            CPA(kbuf0 + (uint32_t)((j * KSTR + k4 * 4) * 4), (const void*)(Kp + j * 16 + k4));
        }
        CPCOMMIT();
    }
    float sumA = 0.f, sumB = 0.f;
    const size_t growA = (size_t)bh * LSEQ + i0 + g;
    const size_t growB = growA + 8;
    const size_t mbase = ((size_t)(bh >> 3) * LSEQ + i0) * LSEQ;

    for (int c = 0; c < 16; c++) {
        CPWAIT0();
        __syncthreads();
        if (c + 1 < 16) {
            uint32_t db = kbuf0 + ((c + 1) & 1) * KBUF;
            const uint4* src = Kp + (size_t)(c + 1) * 128 * 16;
            #pragma unroll
            for (int i = 0; i < 4; i++) {
                int idx = t + i * NT, j = idx >> 4, k4 = idx & 15;
                CPA(db + (uint32_t)((j * KSTR + k4 * 4) * 4), (const void*)(src + j * 16 + k4));
            }
            CPCOMMIT();
        }
        const uint32_t* sK = (const uint32_t*)(smem + OFF_KV + (c & 1) * KBUF);
        float acc[4] = {0.f, 0.f, 0.f, 0.f};
        const int jrow = w * 8 + g;
        #pragma unroll
        for (int ks = 0; ks < 4; ks++) {
            int kw = ks * 16 + 2 * tig;
            uint32_t w0 = sK[jrow * KSTR + kw],     w1 = sK[jrow * KSTR + kw + 1];
            uint32_t w2 = sK[jrow * KSTR + kw + 8], w3 = sK[jrow * KSTR + kw + 9];
            uint32_t b0 = PHI(w0, w1), l0 = PLO(w0, w1);
            uint32_t b1 = PHI(w2, w3), l1 = PLO(w2, w3);
            MMA(acc, qh[ks*4], qh[ks*4+1], qh[ks*4+2], qh[ks*4+3], b0, b1);
            MMA(acc, qh[ks*4], qh[ks*4+1], qh[ks*4+2], qh[ks*4+3], l0, l1);
            MMA(acc, ql[ks*4], ql[ks*4+1], ql[ks*4+2], ql[ks*4+3], b0, b1);
        }
        // fused epilogue: bias + mask + exp, store to sS, accumulate row sums
        const int col = c * 128 + w * 8 + 2 * tig;
        {
            float2 t2 = *(const float2*)(TS + growA * LSEQ + col);
            float2 l2 = *(const float2*)(LS + growA * LSEQ + col);
            unsigned mb = mget2(M, flag, mbase + (size_t)g * LSEQ + col);
            float s0 = (mb & 1u) ? -1e9f : (acc[0] + t2.x + l2.x) * SCALE;
            float s1 = (mb & 2u) ? -1e9f : (acc[1] + t2.y + l2.y) * SCALE;
            float e0 = __expf(s0), e1 = __expf(s1);
            *(float2*)(sS + (size_t)g * SSTR + col) = make_float2(e0, e1);
            sumA += e0 + e1;
        }
        {
            float2 t2 = *(const float2*)(TS + growB * LSEQ + col);
            float2 l2 = *(const float2*)(LS + growB * LSEQ + col);
            unsigned mb = mget2(M, flag, mbase + (size_t)(g + 8) * LSEQ + col);
            float s0 = (mb & 1u) ? -1e9f : (acc[2] + t2.x + l2.x) * SCALE;
            float s1 = (mb & 2u) ? -1e9f : (acc[3] + t2.y + l2.y) * SCALE;
            float e0 = __expf(s0), e1 = __expf(s1);
            *(float2*)(sS + (size_t)(g + 8) * SSTR + col) = make_float2(e0, e1);
            sumB += e0 + e1;
        }
    }
    // reduce row sums: across tig lanes, then across warps
    sumA += __shfl_xor_sync(0xffffffffu, sumA, 1);
    sumA += __shfl_xor_sync(0xffffffffu, sumA, 2);
    sumB += __shfl_xor_sync(0xffffffffu, sumB, 1);
    sumB += __shfl_xor_sync(0xffffffffu, sumB, 2);
    if (tig == 0) { sPart[w * 16 + g] = sumA; sPart[w * 16 + g + 8] = sumB; }
    __syncthreads();
    if (t < 16) {
        float s = 0.f;
        #pragma unroll
        for (int ww = 0; ww < 16; ww++) s += sPart[ww * 16 + t];
        sRow[t] = 1.0f / s;
    }
    __syncthreads();

    // ---- Phase 3: normalize, write P, repack packed bf16 in place ----
    {
        float* Pb = P + ((size_t)bh * LSEQ + i0) * LSEQ;
        #pragma unroll
        for (int it = 0; it < 16; it++) {
            int task = t + it * NT;
            int r = task >> 9, c4 = task & 511;
            float rinv = sRow[r];
            float4 e = ((const float4*)(sS + (size_t)r * SSTR))[c4];
            e.x *= rinv; e.y *= rinv; e.z *= rinv; e.w *= rinv;
            *(float4*)(Pb + (size_t)r * LSEQ + c4 * 4) = e;
            uint4 pw = make_uint4(packsplit(e.x), packsplit(e.y), packsplit(e.z), packsplit(e.w));
            ((uint4*)(sSw + (size_t)r * SSTR))[c4] = pw;
        }
    }

    // ---- Phase 4: O = P V, cp.async double buffer, chunk 128 ----
    const uint4* Vp = (const uint4*)(g_vp + (size_t)bh * 64 * LSEQ);
    const int x = w & 7, h = w >> 3;
    float oc[4][4];
    #pragma unroll
    for (int nt = 0; nt < 4; nt++)
        oc[nt][0] = oc[nt][1] = oc[nt][2] = oc[nt][3] = 0.f;
    {
        #pragma unroll
        for (int i = 0; i < 4; i++) {
            int idx = t + i * NT, dim = idx >> 5, u4 = idx & 31;
            CPA(kbuf0 + (uint32_t)((dim * VSTR2 + u4 * 4) * 4),
                (const void*)(Vp + (size_t)dim * 512 + u4));
        }
        CPCOMMIT();
    }
    for (int c = 0; c < 16; c++) {
        CPWAIT0();
        __syncthreads();
        if (c + 1 < 16) {
            uint32_t db = kbuf0 + ((c + 1) & 1) * VBUF;
            #pragma unroll
            for (int i = 0; i < 4; i++) {
                int idx = t + i * NT, dim = idx >> 5, u4 = idx & 31;
                CPA(db + (uint32_t)((dim * VSTR2 + u4 * 4) * 4),
                    (const void*)(Vp + (size_t)dim * 512 + (c + 1) * 32 + u4));
            }
            CPCOMMIT();
        }
        const uint32_t* sV = (const uint32_t*)(smem + OFF_KV + (c & 1) * VBUF);
        int ac = c * 128 + x * 16 + 2 * tig;
        uint32_t w00 = sSw[(size_t)g * SSTR + ac],         w01 = sSw[(size_t)g * SSTR + ac + 1];
        uint32_t w10 = sSw[(size_t)(g+8) * SSTR + ac],     w11 = sSw[(size_t)(g+8) * SSTR + ac + 1];
        uint32_t w20 = sSw[(size_t)g * SSTR + ac + 8],     w21 = sSw[(size_t)g * SSTR + ac + 9];
        uint32_t w30 = sSw[(size_t)(g+8) * SSTR + ac + 8], w31 = sSw[(size_t)(g+8) * SSTR + ac + 9];
        uint32_t ah0 = PHI(w00,w01), ah1 = PHI(w10,w11), ah2 = PHI(w20,w21), ah3 = PHI(w30,w31);
        uint32_t al0 = PLO(w00,w01), al1 = PLO(w10,w11), al2 = PLO(w20,w21), al3 = PLO(w30,w31);
        int jb2 = x * 16 + 2 * tig;
        #pragma unroll
        for (int nt = 0; nt < 4; nt++) {
            int dim = h * 32 + 8 * nt + g;
            uint32_t v0 = sV[dim * VSTR2 + jb2],     v1 = sV[dim * VSTR2 + jb2 + 1];
            uint32_t v2 = sV[dim * VSTR2 + jb2 + 8], v3 = sV[dim * VSTR2 + jb2 + 9];
            uint32_t bh0 = PHI(v0, v1), bl0 = PLO(v0, v1);
            uint32_t bh1 = PHI(v2, v3), bl1 = PLO(v2, v3);
            MMA(oc[nt], ah0, ah1, ah2, ah3, bh0, bh1);
            MMA(oc[nt], ah0, ah1, ah2, ah3, bl0, bl1);
            MMA(oc[nt], al0, al1, al2, al3, bh0, bh1);
        }
    }
    // cross-window reduce via the (now free) V buffer region: part[x][row][dim]
    __syncthreads();
    {
        float* part = (float*)(smem + OFF_KV);
        #pragma unroll
        for (int nt = 0; nt < 4; nt++) {
            int dimb = h * 32 + 8 * nt + 2 * tig;
            *(float2*)(part + x * 1024 + g * 64 + dimb)       = make_float2(oc[nt][0], oc[nt][1]);
            *(float2*)(part + x * 1024 + (g + 8) * 64 + dimb) = make_float2(oc[nt][2], oc[nt][3]);
        }
    }
    __syncthreads();
    {
        const float* part = (const float*)(smem + OFF_KV);
        #pragma unroll
        for (int i = 0; i < 2; i++) {
            int idx = t + i * NT;               // 0..1023
            int row = idx >> 6, dim = idx & 63;
            float s = 0.f;
            #pragma unroll
            for (int xx = 0; xx < 8; xx++) s += part[xx * 1024 + row * 64 + dim];
            O[((size_t)bh * LSEQ + i0 + row) * 64 + dim] = s;
        }
    }
}

extern "C" void kernel_launch(void* const* d_in, const int* in_sizes, int n_in,
                              void* d_out, int out_size)
{
    const float* Q  = (const float*)d_in[0];
    const float* K  = (const float*)d_in[1];
    const float* V  = (const float*)d_in[2];
    const unsigned char* M = (const unsigned char*)d_in[3];
    const float* TS = (const float*)d_in[4];
    const float* LS = (const float*)d_in[5];
    float* out = (float*)d_out;
    float* O = out;
    float* P = out + (size_t)NBH * LSEQ * 64;

    prep_kernel<<<1536, 256>>>(Q, K, V);
    cudaFuncSetAttribute(raa_kernel, cudaFuncAttributeMaxDynamicSharedMemorySize, SMEM_BYTES);
    dim3 grid(LSEQ / 16, NBH);
    raa_kernel<<<grid, NT, SMEM_BYTES>>>(M, TS, LS, O, P);
}

// round 10
// speedup vs baseline: 1.1929x; 1.1929x over previous
#include <cuda_runtime.h>
#include <cuda_bf16.h>
#include <cstdint>

#define LSEQ 2048
#define NBH  16
#define NT   512
#define SCALE 0.07216878364870323f   // 1/sqrt(3*64)
#define SSTR 2052
#define KSTR 68
#define VSTR2 132

#define OFF_KV 131328                // sS = 16*2052*4
#define KBUF   34816                 // 128*68*4
#define VBUF   33792                 // 64*132*4
#define OFF_Q  200960                // OFF_KV + 2*KBUF
#define SMEM_BYTES 205312

__device__ uint32_t g_qp[(size_t)NBH * LSEQ * 64];
__device__ uint32_t g_kp[(size_t)NBH * LSEQ * 64];
__device__ uint32_t g_vp[(size_t)NBH * 64 * LSEQ];   // [bh][dim][j]

__device__ __forceinline__ uint32_t packsplit(float x) {
    __nv_bfloat16 h = __float2bfloat16(x);
    float hf = __bfloat162float(h);
    __nv_bfloat16 l = __float2bfloat16(x - hf);
    unsigned short hs = *(unsigned short*)&h, ls = *(unsigned short*)&l;
    return (uint32_t)hs | ((uint32_t)ls << 16);
}
__device__ __forceinline__ uint32_t smem_u32(const void* p) {
    uint32_t a;
    asm("{ .reg .u64 t; cvta.to.shared.u64 t, %1; cvt.u32.u64 %0, t; }" : "=r"(a) : "l"(p));
    return a;
}
#define PHI(w0,w1) __byte_perm((w0), (w1), 0x5410)
#define PLO(w0,w1) __byte_perm((w0), (w1), 0x7632)
#define MMA(c, a0,a1,a2,a3, b0,b1) \
  asm volatile("mma.sync.aligned.m16n8k16.row.col.f32.bf16.bf16.f32 " \
    "{%0,%1,%2,%3}, {%4,%5,%6,%7}, {%8,%9}, {%0,%1,%2,%3};" \
    : "+f"((c)[0]), "+f"((c)[1]), "+f"((c)[2]), "+f"((c)[3]) \
    : "r"(a0), "r"(a1), "r"(a2), "r"(a3), "r"(b0), "r"(b1))
#define CPA(dst, src) asm volatile("cp.async.cg.shared.global [%0], [%1], 16;" :: "r"(dst), "l"(src))
#define CPCOMMIT()    asm volatile("cp.async.commit_group;" ::: "memory")
#define CPWAIT0()     asm volatile("cp.async.wait_group 0;" ::: "memory")

// ---------------- prep: pack Q/K; transpose+pack V ----------------
__global__ void prep_kernel(const float* __restrict__ Q, const float* __restrict__ K,
                            const float* __restrict__ V)
{
    const int t = threadIdx.x;
    if (blockIdx.x < 1024) {
        #pragma unroll
        for (int i = 0; i < 2; i++) {
            size_t idx4 = (size_t)blockIdx.x * 512 + t + (size_t)i * 256;
            float4 q = ((const float4*)Q)[idx4];
            ((uint4*)g_qp)[idx4] = make_uint4(packsplit(q.x), packsplit(q.y),
                                             packsplit(q.z), packsplit(q.w));
            float4 k = ((const float4*)K)[idx4];
            ((uint4*)g_kp)[idx4] = make_uint4(packsplit(k.x), packsplit(k.y),
                                             packsplit(k.z), packsplit(k.w));
        }
    } else {
        __shared__ float sT[64 * 65];
        int bi = blockIdx.x - 1024, bh = bi >> 5, jt = bi & 31;
        const float* Vb = V + ((size_t)bh * LSEQ + jt * 64) * 64;
        #pragma unroll
        for (int i = 0; i < 4; i++) {
            int q = t + i * 256, j = q >> 4, n4 = (q & 15) * 4;
            float4 v = *(const float4*)(Vb + (size_t)j * 64 + n4);
            sT[(n4+0)*65 + j] = v.x; sT[(n4+1)*65 + j] = v.y;
            sT[(n4+2)*65 + j] = v.z; sT[(n4+3)*65 + j] = v.w;
        }
        __syncthreads();
        #pragma unroll
        for (int i = 0; i < 4; i++) {
            int q = t + i * 256, dim = q >> 4, j4 = (q & 15) * 4;
            uint4 pw = make_uint4(packsplit(sT[dim*65 + j4]),
                                  packsplit(sT[dim*65 + j4 + 1]),
                                  packsplit(sT[dim*65 + j4 + 2]),
                                  packsplit(sT[dim*65 + j4 + 3]));
            *(uint4*)(g_vp + ((size_t)bh * 64 + dim) * LSEQ + jt * 64 + j4) = pw;
        }
    }
}

// ---------------- main fused kernel ----------------
__global__ __launch_bounds__(NT, 1)
void raa_kernel(const unsigned char* __restrict__ M,
                const float* __restrict__ TS, const float* __restrict__ LS,
                float* __restrict__ O, float* __restrict__ P)
{
    extern __shared__ char smem[];
    float*    sS  = (float*)smem;
    uint32_t* sSw = (uint32_t*)smem;
    uint32_t* sQ  = (uint32_t*)(smem + OFF_Q);
    __shared__ float sRow[16];
    __shared__ int   sFlag;

    const int t = threadIdx.x, w = t >> 5, lane = t & 31;
    const int g = lane >> 2, tig = lane & 3;
    const int bh = blockIdx.y, i0 = blockIdx.x * 16;

    if (t == 0) {
        const int* mi = (const int*)M; const float* mf = (const float*)M;
        bool okI = true, okF = true;
        for (int i = 0; i < 64; i++) {
            int vi = mi[i]; float vf = mf[i];
            if (vi != 0 && vi != 1)     okI = false;
            if (vf != 0.f && vf != 1.f) okF = false;
        }
        sFlag = okI ? 1 : (okF ? 2 : 0);
    }
    if (t < 256) {
        int row = t >> 4, k4 = (t & 15) * 4;
        uint4 pw = *((const uint4*)(g_qp + ((size_t)bh * LSEQ + i0) * 64) + t);
        *(uint4*)(sQ + row * KSTR + k4) = pw;
    }
    __syncthreads();
    const int flag = sFlag;

    // Q A-frags resident through phase 1
    uint32_t qh[16], ql[16];
    #pragma unroll
    for (int ks = 0; ks < 4; ks++) {
        int c0 = ks * 16 + 2 * tig;
        uint32_t w00 = sQ[g * KSTR + c0],           w01 = sQ[g * KSTR + c0 + 1];
        uint32_t w10 = sQ[(g + 8) * KSTR + c0],     w11 = sQ[(g + 8) * KSTR + c0 + 1];
        uint32_t w20 = sQ[g * KSTR + c0 + 8],       w21 = sQ[g * KSTR + c0 + 9];
        uint32_t w30 = sQ[(g + 8) * KSTR + c0 + 8], w31 = sQ[(g + 8) * KSTR + c0 + 9];
        qh[ks*4+0] = PHI(w00, w01); ql[ks*4+0] = PLO(w00, w01);
        qh[ks*4+1] = PHI(w10, w11); ql[ks*4+1] = PLO(w10, w11);
        qh[ks*4+2] = PHI(w20, w21); ql[ks*4+2] = PLO(w20, w21);
        qh[ks*4+3] = PHI(w30, w31); ql[ks*4+3] = PLO(w30, w31);
    }

    // ---- Phase 1: raw S = Q K^T, cp.async double-buffered K chunks ----
    const uint4* Kp = (const uint4*)(g_kp + (size_t)bh * LSEQ * 64);
    const uint32_t kbuf0 = smem_u32(smem + OFF_KV);
    {
        #pragma unroll
        for (int i = 0; i < 4; i++) {
            int idx = t + i * NT, j = idx >> 4, k4 = idx & 15;
            CPA(kbuf0 + (uint32_t)((j * KSTR + k4 * 4) * 4), (const void*)(Kp + j * 16 + k4));
        }
        CPCOMMIT();
    }
    for (int c = 0; c < 16; c++) {
        CPWAIT0();
        __syncthreads();
        if (c + 1 < 16) {
            uint32_t db = kbuf0 + ((c + 1) & 1) * KBUF;
            const uint4* src = Kp + (size_t)(c + 1) * 128 * 16;
            #pragma unroll
            for (int i = 0; i < 4; i++) {
                int idx = t + i * NT, j = idx >> 4, k4 = idx & 15;
                CPA(db + (uint32_t)((j * KSTR + k4 * 4) * 4), (const void*)(src + j * 16 + k4));
            }
            CPCOMMIT();
        }
        const uint32_t* sK = (const uint32_t*)(smem + OFF_KV + (c & 1) * KBUF);
        float acc[4] = {0.f, 0.f, 0.f, 0.f};
        const int jrow = w * 8 + g;
        #pragma unroll
        for (int ks = 0; ks < 4; ks++) {
            int kw = ks * 16 + 2 * tig;
            uint32_t w0 = sK[jrow * KSTR + kw],     w1 = sK[jrow * KSTR + kw + 1];
            uint32_t w2 = sK[jrow * KSTR + kw + 8], w3 = sK[jrow * KSTR + kw + 9];
            uint32_t b0 = PHI(w0, w1), l0 = PLO(w0, w1);
            uint32_t b1 = PHI(w2, w3), l1 = PLO(w2, w3);
            MMA(acc, qh[ks*4], qh[ks*4+1], qh[ks*4+2], qh[ks*4+3], b0, b1);
            MMA(acc, qh[ks*4], qh[ks*4+1], qh[ks*4+2], qh[ks*4+3], l0, l1);
            MMA(acc, ql[ks*4], ql[ks*4+1], ql[ks*4+2], ql[ks*4+3], b0, b1);
        }
        const int col = c * 128 + w * 8 + 2 * tig;
        *(float2*)(sS + (size_t)g * SSTR + col)       = make_float2(acc[0], acc[1]);
        *(float2*)(sS + (size_t)(g + 8) * SSTR + col) = make_float2(acc[2], acc[3]);
    }
    __syncthreads();

    // ---- Phase 2 (single pass, coalesced): bias + mask + exp + row sum ----
    {
        const int row = w;
        float* sSr = sS + (size_t)row * SSTR;
        const size_t grow = (size_t)bh * LSEQ + i0 + row;
        const float* tsr = TS + grow * LSEQ;
        const float* lsr = LS + grow * LSEQ;
        const size_t mrow = ((size_t)(bh >> 3) * LSEQ + i0 + row) * LSEQ;
        float sum = 0.f;
        for (int c4 = lane; c4 < 512; c4 += 32) {
            float4 s = ((const float4*)sSr)[c4];
            float4 t4 = *(const float4*)(tsr + c4 * 4);
            float4 l4 = *(const float4*)(lsr + c4 * 4);
            unsigned mb;
            if (flag == 1) { int4 v = *(const int4*)((const int*)M + mrow + c4 * 4);
                mb = (v.x?1u:0)|(v.y?2u:0)|(v.z?4u:0)|(v.w?8u:0); }
            else if (flag == 0) { uchar4 v = *(const uchar4*)(M + mrow + c4 * 4);
                mb = (v.x?1u:0)|(v.y?2u:0)|(v.z?4u:0)|(v.w?8u:0); }
            else { float4 v = *(const float4*)((const float*)M + mrow + c4 * 4);
                mb = (v.x!=0.f?1u:0)|(v.y!=0.f?2u:0)|(v.z!=0.f?4u:0)|(v.w!=0.f?8u:0); }
            s.x = (mb & 1u) ? 0.f : __expf((s.x + t4.x + l4.x) * SCALE);
            s.y = (mb & 2u) ? 0.f : __expf((s.y + t4.y + l4.y) * SCALE);
            s.z = (mb & 4u) ? 0.f : __expf((s.z + t4.z + l4.z) * SCALE);
            s.w = (mb & 8u) ? 0.f : __expf((s.w + t4.w + l4.w) * SCALE);
            ((float4*)sSr)[c4] = s;
            sum += (s.x + s.y) + (s.z + s.w);
        }
        #pragma unroll
        for (int k = 16; k >= 1; k >>= 1)
            sum += __shfl_xor_sync(0xffffffffu, sum, k);
        if (lane == 0) sRow[row] = 1.0f / sum;
    }
    __syncthreads();

    // ---- Phase 3: normalize, write P, repack packed bf16 in place ----
    {
        float* Pb = P + ((size_t)bh * LSEQ + i0) * LSEQ;
        #pragma unroll
        for (int it = 0; it < 16; it++) {
            int task = t + it * NT;
            int r = task >> 9, c4 = task & 511;
            float rinv = sRow[r];
            float4 e = ((const float4*)(sS + (size_t)r * SSTR))[c4];
            e.x *= rinv; e.y *= rinv; e.z *= rinv; e.w *= rinv;
            *(float4*)(Pb + (size_t)r * LSEQ + c4 * 4) = e;
            uint4 pw = make_uint4(packsplit(e.x), packsplit(e.y), packsplit(e.z), packsplit(e.w));
            ((uint4*)(sSw + (size_t)r * SSTR))[c4] = pw;
        }
    }

    // ---- Phase 4: O = P V, cp.async double buffer, chunk 128 ----
    const uint4* Vp = (const uint4*)(g_vp + (size_t)bh * 64 * LSEQ);
    const int x = w & 7, h = w >> 3;
    float oc[4][4];
    #pragma unroll
    for (int nt = 0; nt < 4; nt++)
        oc[nt][0] = oc[nt][1] = oc[nt][2] = oc[nt][3] = 0.f;
    {
        #pragma unroll
        for (int i = 0; i < 4; i++) {
            int idx = t + i * NT, dim = idx >> 5, u4 = idx & 31;
            CPA(kbuf0 + (uint32_t)((dim * VSTR2 + u4 * 4) * 4),
                (const void*)(Vp + (size_t)dim * 512 + u4));
        }
        CPCOMMIT();
    }
    for (int c = 0; c < 16; c++) {
        CPWAIT0();
        __syncthreads();
        if (c + 1 < 16) {
            uint32_t db = kbuf0 + ((c + 1) & 1) * VBUF;
            #pragma unroll
            for (int i = 0; i < 4; i++) {
                int idx = t + i * NT, dim = idx >> 5, u4 = idx & 31;
                CPA(db + (uint32_t)((dim * VSTR2 + u4 * 4) * 4),
                    (const void*)(Vp + (size_t)dim * 512 + (c + 1) * 32 + u4));
            }
            CPCOMMIT();
        }
        const uint32_t* sV = (const uint32_t*)(smem + OFF_KV + (c & 1) * VBUF);
        int ac = c * 128 + x * 16 + 2 * tig;
        uint32_t w00 = sSw[(size_t)g * SSTR + ac],         w01 = sSw[(size_t)g * SSTR + ac + 1];
        uint32_t w10 = sSw[(size_t)(g+8) * SSTR + ac],     w11 = sSw[(size_t)(g+8) * SSTR + ac + 1];
        uint32_t w20 = sSw[(size_t)g * SSTR + ac + 8],     w21 = sSw[(size_t)g * SSTR + ac + 9];
        uint32_t w30 = sSw[(size_t)(g+8) * SSTR + ac + 8], w31 = sSw[(size_t)(g+8) * SSTR + ac + 9];
        uint32_t ah0 = PHI(w00,w01), ah1 = PHI(w10,w11), ah2 = PHI(w20,w21), ah3 = PHI(w30,w31);
        uint32_t al0 = PLO(w00,w01), al1 = PLO(w10,w11), al2 = PLO(w20,w21), al3 = PLO(w30,w31);
        int jb2 = x * 16 + 2 * tig;
        #pragma unroll
        for (int nt = 0; nt < 4; nt++) {
            int dim = h * 32 + 8 * nt + g;
            uint32_t v0 = sV[dim * VSTR2 + jb2],     v1 = sV[dim * VSTR2 + jb2 + 1];
            uint32_t v2 = sV[dim * VSTR2 + jb2 + 8], v3 = sV[dim * VSTR2 + jb2 + 9];
            uint32_t bh0 = PHI(v0, v1), bl0 = PLO(v0, v1);
            uint32_t bh1 = PHI(v2, v3), bl1 = PLO(v2, v3);
            MMA(oc[nt], ah0, ah1, ah2, ah3, bh0, bh1);
            MMA(oc[nt], ah0, ah1, ah2, ah3, bl0, bl1);
            MMA(oc[nt], al0, al1, al2, al3, bh0, bh1);
        }
    }
    // cross-window reduce via freed staging region
    __syncthreads();
    {
        float* part = (float*)(smem + OFF_KV);
        #pragma unroll
        for (int nt = 0; nt < 4; nt++) {
            int dimb = h * 32 + 8 * nt + 2 * tig;
            *(float2*)(part + x * 1024 + g * 64 + dimb)       = make_float2(oc[nt][0], oc[nt][1]);
            *(float2*)(part + x * 1024 + (g + 8) * 64 + dimb) = make_float2(oc[nt][2], oc[nt][3]);
        }
    }
    __syncthreads();
    {
        const float* part = (const float*)(smem + OFF_KV);
        #pragma unroll
        for (int i = 0; i < 2; i++) {
            int idx = t + i * NT;               // 0..1023
            int row = idx >> 6, dim = idx & 63;
            float s = 0.f;
            #pragma unroll
            for (int xx = 0; xx < 8; xx++) s += part[xx * 1024 + row * 64 + dim];
            O[((size_t)bh * LSEQ + i0 + row) * 64 + dim] = s;
        }
    }
}

extern "C" void kernel_launch(void* const* d_in, const int* in_sizes, int n_in,
                              void* d_out, int out_size)
{
    const float* Q  = (const float*)d_in[0];
    const float* K  = (const float*)d_in[1];
    const float* V  = (const float*)d_in[2];
    const unsigned char* M = (const unsigned char*)d_in[3];
    const float* TS = (const float*)d_in[4];
    const float* LS = (const float*)d_in[5];
    float* out = (float*)d_out;
    float* O = out;
    float* P = out + (size_t)NBH * LSEQ * 64;

    prep_kernel<<<1536, 256>>>(Q, K, V);
    cudaFuncSetAttribute(raa_kernel, cudaFuncAttributeMaxDynamicSharedMemorySize, SMEM_BYTES);
    dim3 grid(LSEQ / 16, NBH);
    raa_kernel<<<grid, NT, SMEM_BYTES>>>(M, TS, LS, O, P);
}

// round 11
// speedup vs baseline: 1.2527x; 1.0501x over previous
#include <cuda_runtime.h>
#include <cuda_bf16.h>
#include <cstdint>

#define LSEQ 2048
#define NBH  16
#define NT   1024
#define SCALE 0.07216878364870323f   // 1/sqrt(3*64)
#define SSTR 2052
#define KSTR 68
#define VSTR2 132

#define OFF_KV 131328                // sS = 16*2052*4
#define KBUF   34816                 // 128*68*4
#define VBUF   33792                 // 64*132*4
#define OFF_Q  200960                // OFF_KV + 2*KBUF
#define SMEM_BYTES 205312

__device__ uint32_t g_qp[(size_t)NBH * LSEQ * 64];
__device__ uint32_t g_kp[(size_t)NBH * LSEQ * 64];
__device__ uint32_t g_vp[(size_t)NBH * 64 * LSEQ];   // [bh][dim][j]

__device__ __forceinline__ uint32_t packsplit(float x) {
    __nv_bfloat16 h = __float2bfloat16(x);
    float hf = __bfloat162float(h);
    __nv_bfloat16 l = __float2bfloat16(x - hf);
    unsigned short hs = *(unsigned short*)&h, ls = *(unsigned short*)&l;
    return (uint32_t)hs | ((uint32_t)ls << 16);
}
__device__ __forceinline__ uint32_t smem_u32(const void* p) {
    uint32_t a;
    asm("{ .reg .u64 t; cvta.to.shared.u64 t, %1; cvt.u32.u64 %0, t; }" : "=r"(a) : "l"(p));
    return a;
}
#define PHI(w0,w1) __byte_perm((w0), (w1), 0x5410)
#define PLO(w0,w1) __byte_perm((w0), (w1), 0x7632)
#define MMA(c, a0,a1,a2,a3, b0,b1) \
  asm volatile("mma.sync.aligned.m16n8k16.row.col.f32.bf16.bf16.f32 " \
    "{%0,%1,%2,%3}, {%4,%5,%6,%7}, {%8,%9}, {%0,%1,%2,%3};" \
    : "+f"((c)[0]), "+f"((c)[1]), "+f"((c)[2]), "+f"((c)[3]) \
    : "r"(a0), "r"(a1), "r"(a2), "r"(a3), "r"(b0), "r"(b1))
#define CPA(dst, src) asm volatile("cp.async.cg.shared.global [%0], [%1], 16;" :: "r"(dst), "l"(src))
#define CPCOMMIT()    asm volatile("cp.async.commit_group;" ::: "memory")
#define CPWAIT0()     asm volatile("cp.async.wait_group 0;" ::: "memory")

// ---------------- prep: pack Q/K; transpose+pack V ----------------
__global__ void prep_kernel(const float* __restrict__ Q, const float* __restrict__ K,
                            const float* __restrict__ V)
{
    const int t = threadIdx.x;
    if (blockIdx.x < 1024) {
        #pragma unroll
        for (int i = 0; i < 2; i++) {
            size_t idx4 = (size_t)blockIdx.x * 512 + t + (size_t)i * 256;
            float4 q = ((const float4*)Q)[idx4];
            ((uint4*)g_qp)[idx4] = make_uint4(packsplit(q.x), packsplit(q.y),
                                             packsplit(q.z), packsplit(q.w));
            float4 k = ((const float4*)K)[idx4];
            ((uint4*)g_kp)[idx4] = make_uint4(packsplit(k.x), packsplit(k.y),
                                             packsplit(k.z), packsplit(k.w));
        }
    } else {
        __shared__ float sT[64 * 65];
        int bi = blockIdx.x - 1024, bh = bi >> 5, jt = bi & 31;
        const float* Vb = V + ((size_t)bh * LSEQ + jt * 64) * 64;
        #pragma unroll
        for (int i = 0; i < 4; i++) {
            int q = t + i * 256, j = q >> 4, n4 = (q & 15) * 4;
            float4 v = *(const float4*)(Vb + (size_t)j * 64 + n4);
            sT[(n4+0)*65 + j] = v.x; sT[(n4+1)*65 + j] = v.y;
            sT[(n4+2)*65 + j] = v.z; sT[(n4+3)*65 + j] = v.w;
        }
        __syncthreads();
        #pragma unroll
        for (int i = 0; i < 4; i++) {
            int q = t + i * 256, dim = q >> 4, j4 = (q & 15) * 4;
            uint4 pw = make_uint4(packsplit(sT[dim*65 + j4]),
                                  packsplit(sT[dim*65 + j4 + 1]),
                                  packsplit(sT[dim*65 + j4 + 2]),
                                  packsplit(sT[dim*65 + j4 + 3]));
            *(uint4*)(g_vp + ((size_t)bh * 64 + dim) * LSEQ + jt * 64 + j4) = pw;
        }
    }
}

// ---------------- main fused kernel: 1024 threads ----------------
__global__ __launch_bounds__(NT, 1)
void raa_kernel(const unsigned char* __restrict__ M,
                const float* __restrict__ TS, const float* __restrict__ LS,
                float* __restrict__ O, float* __restrict__ P)
{
    extern __shared__ char smem[];
    float*    sS  = (float*)smem;
    uint32_t* sSw = (uint32_t*)smem;
    uint32_t* sQ  = (uint32_t*)(smem + OFF_Q);
    __shared__ float sRow[16];
    __shared__ float sPart[32];
    __shared__ int   sFlag;

    const int t = threadIdx.x, w = t >> 5, lane = t & 31;
    const int g = lane >> 2, tig = lane & 3;
    const int bh = blockIdx.y, i0 = blockIdx.x * 16;

    if (t == 0) {
        const int* mi = (const int*)M; const float* mf = (const float*)M;
        bool okI = true, okF = true;
        for (int i = 0; i < 64; i++) {
            int vi = mi[i]; float vf = mf[i];
            if (vi != 0 && vi != 1)     okI = false;
            if (vf != 0.f && vf != 1.f) okF = false;
        }
        sFlag = okI ? 1 : (okF ? 2 : 0);
    }
    if (t < 256) {
        int row = t >> 4, k4 = (t & 15) * 4;
        uint4 pw = *((const uint4*)(g_qp + ((size_t)bh * LSEQ + i0) * 64) + t);
        *(uint4*)(sQ + row * KSTR + k4) = pw;
    }
    __syncthreads();
    const int flag = sFlag;

    // ---- Phase 1: raw S = Q K^T; 2 warps per n-tile (k-split) ----
    const int nt1 = w & 15, kh = w >> 4;
    uint32_t qh[8], ql[8];
    #pragma unroll
    for (int kkl = 0; kkl < 2; kkl++) {
        int ks = kh * 2 + kkl;
        int c0 = ks * 16 + 2 * tig;
        uint32_t w00 = sQ[g * KSTR + c0],           w01 = sQ[g * KSTR + c0 + 1];
        uint32_t w10 = sQ[(g + 8) * KSTR + c0],     w11 = sQ[(g + 8) * KSTR + c0 + 1];
        uint32_t w20 = sQ[g * KSTR + c0 + 8],       w21 = sQ[g * KSTR + c0 + 9];
        uint32_t w30 = sQ[(g + 8) * KSTR + c0 + 8], w31 = sQ[(g + 8) * KSTR + c0 + 9];
        qh[kkl*4+0] = PHI(w00, w01); ql[kkl*4+0] = PLO(w00, w01);
        qh[kkl*4+1] = PHI(w10, w11); ql[kkl*4+1] = PLO(w10, w11);
        qh[kkl*4+2] = PHI(w20, w21); ql[kkl*4+2] = PLO(w20, w21);
        qh[kkl*4+3] = PHI(w30, w31); ql[kkl*4+3] = PLO(w30, w31);
    }

    const uint4* Kp = (const uint4*)(g_kp + (size_t)bh * LSEQ * 64);
    const uint32_t kbuf0 = smem_u32(smem + OFF_KV);
    {
        #pragma unroll
        for (int i = 0; i < 2; i++) {
            int idx = t + i * NT, j = idx >> 4, k4 = idx & 15;
            CPA(kbuf0 + (uint32_t)((j * KSTR + k4 * 4) * 4), (const void*)(Kp + j * 16 + k4));
        }
        CPCOMMIT();
    }
    for (int c = 0; c < 16; c++) {
        CPWAIT0();
        __syncthreads();
        if (c + 1 < 16) {
            uint32_t db = kbuf0 + ((c + 1) & 1) * KBUF;
            const uint4* src = Kp + (size_t)(c + 1) * 128 * 16;
            #pragma unroll
            for (int i = 0; i < 2; i++) {
                int idx = t + i * NT, j = idx >> 4, k4 = idx & 15;
                CPA(db + (uint32_t)((j * KSTR + k4 * 4) * 4), (const void*)(src + j * 16 + k4));
            }
            CPCOMMIT();
        }
        const uint32_t* sK = (const uint32_t*)(smem + OFF_KV + (c & 1) * KBUF);
        float acc[4] = {0.f, 0.f, 0.f, 0.f};
        const int jrow = nt1 * 8 + g;
        #pragma unroll
        for (int kkl = 0; kkl < 2; kkl++) {
            int ks = kh * 2 + kkl;
            int kw = ks * 16 + 2 * tig;
            uint32_t w0 = sK[jrow * KSTR + kw],     w1 = sK[jrow * KSTR + kw + 1];
            uint32_t w2 = sK[jrow * KSTR + kw + 8], w3 = sK[jrow * KSTR + kw + 9];
            uint32_t b0 = PHI(w0, w1), l0 = PLO(w0, w1);
            uint32_t b1 = PHI(w2, w3), l1 = PLO(w2, w3);
            MMA(acc, qh[kkl*4], qh[kkl*4+1], qh[kkl*4+2], qh[kkl*4+3], b0, b1);
            MMA(acc, qh[kkl*4], qh[kkl*4+1], qh[kkl*4+2], qh[kkl*4+3], l0, l1);
            MMA(acc, ql[kkl*4], ql[kkl*4+1], ql[kkl*4+2], ql[kkl*4+3], b0, b1);
        }
        const int col = c * 128 + nt1 * 8 + 2 * tig;
        if (kh == 1) {
            *(float2*)(sS + (size_t)g * SSTR + col)       = make_float2(acc[0], acc[1]);
            *(float2*)(sS + (size_t)(g + 8) * SSTR + col) = make_float2(acc[2], acc[3]);
        }
        __syncthreads();
        if (kh == 0) {
            float2 pA = *(const float2*)(sS + (size_t)g * SSTR + col);
            float2 pB = *(const float2*)(sS + (size_t)(g + 8) * SSTR + col);
            *(float2*)(sS + (size_t)g * SSTR + col)       = make_float2(acc[0] + pA.x, acc[1] + pA.y);
            *(float2*)(sS + (size_t)(g + 8) * SSTR + col) = make_float2(acc[2] + pB.x, acc[3] + pB.y);
        }
    }
    __syncthreads();

    // ---- Phase 2: bias + mask + exp + row sum (2 warps per row) ----
    {
        const int row = w >> 1, half = w & 1;
        float* sSr = sS + (size_t)row * SSTR;
        const size_t grow = (size_t)bh * LSEQ + i0 + row;
        const float* tsr = TS + grow * LSEQ;
        const float* lsr = LS + grow * LSEQ;
        const size_t mrow = ((size_t)(bh >> 3) * LSEQ + i0 + row) * LSEQ;
        float sum = 0.f;
        for (int c4 = lane + half * 32; c4 < 512; c4 += 64) {
            float4 s = ((const float4*)sSr)[c4];
            float4 t4 = *(const float4*)(tsr + c4 * 4);
            float4 l4 = *(const float4*)(lsr + c4 * 4);
            unsigned mb;
            if (flag == 1) { int4 v = *(const int4*)((const int*)M + mrow + c4 * 4);
                mb = (v.x?1u:0)|(v.y?2u:0)|(v.z?4u:0)|(v.w?8u:0); }
            else if (flag == 0) { uchar4 v = *(const uchar4*)(M + mrow + c4 * 4);
                mb = (v.x?1u:0)|(v.y?2u:0)|(v.z?4u:0)|(v.w?8u:0); }
            else { float4 v = *(const float4*)((const float*)M + mrow + c4 * 4);
                mb = (v.x!=0.f?1u:0)|(v.y!=0.f?2u:0)|(v.z!=0.f?4u:0)|(v.w!=0.f?8u:0); }
            s.x = (mb & 1u) ? 0.f : __expf((s.x + t4.x + l4.x) * SCALE);
            s.y = (mb & 2u) ? 0.f : __expf((s.y + t4.y + l4.y) * SCALE);
            s.z = (mb & 4u) ? 0.f : __expf((s.z + t4.z + l4.z) * SCALE);
            s.w = (mb & 8u) ? 0.f : __expf((s.w + t4.w + l4.w) * SCALE);
            ((float4*)sSr)[c4] = s;
            sum += (s.x + s.y) + (s.z + s.w);
        }
        #pragma unroll
        for (int k = 16; k >= 1; k >>= 1)
            sum += __shfl_xor_sync(0xffffffffu, sum, k);
        if (lane == 0) sPart[w] = sum;
    }
    __syncthreads();
    if (t < 16) sRow[t] = 1.0f / (sPart[2 * t] + sPart[2 * t + 1]);
    __syncthreads();

    // ---- Phase 3: normalize, write P, repack packed bf16 in place ----
    {
        float* Pb = P + ((size_t)bh * LSEQ + i0) * LSEQ;
        #pragma unroll
        for (int it = 0; it < 8; it++) {
            int task = t + it * NT;
            int r = task >> 9, c4 = task & 511;
            float rinv = sRow[r];
            float4 e = ((const float4*)(sS + (size_t)r * SSTR))[c4];
            e.x *= rinv; e.y *= rinv; e.z *= rinv; e.w *= rinv;
            *(float4*)(Pb + (size_t)r * LSEQ + c4 * 4) = e;
            uint4 pw = make_uint4(packsplit(e.x), packsplit(e.y), packsplit(e.z), packsplit(e.w));
            ((uint4*)(sSw + (size_t)r * SSTR))[c4] = pw;
        }
    }

    // ---- Phase 4: O = P V; warp = (j-window, dim-quarter) ----
    const uint4* Vp = (const uint4*)(g_vp + (size_t)bh * 64 * LSEQ);
    const int x = w & 7, q4 = w >> 3;    // 8 windows x 4 dim-quarters
    float oc[2][4];
    #pragma unroll
    for (int nt = 0; nt < 2; nt++)
        oc[nt][0] = oc[nt][1] = oc[nt][2] = oc[nt][3] = 0.f;
    {
        #pragma unroll
        for (int i = 0; i < 2; i++) {
            int idx = t + i * NT, dim = idx >> 5, u4 = idx & 31;
            CPA(kbuf0 + (uint32_t)((dim * VSTR2 + u4 * 4) * 4),
                (const void*)(Vp + (size_t)dim * 512 + u4));
        }
        CPCOMMIT();
    }
    for (int c = 0; c < 16; c++) {
        CPWAIT0();
        __syncthreads();
        if (c + 1 < 16) {
            uint32_t db = kbuf0 + ((c + 1) & 1) * VBUF;
            #pragma unroll
            for (int i = 0; i < 2; i++) {
                int idx = t + i * NT, dim = idx >> 5, u4 = idx & 31;
                CPA(db + (uint32_t)((dim * VSTR2 + u4 * 4) * 4),
                    (const void*)(Vp + (size_t)dim * 512 + (c + 1) * 32 + u4));
            }
            CPCOMMIT();
        }
        const uint32_t* sV = (const uint32_t*)(smem + OFF_KV + (c & 1) * VBUF);
        int ac = c * 128 + x * 16 + 2 * tig;
        uint32_t w00 = sSw[(size_t)g * SSTR + ac],         w01 = sSw[(size_t)g * SSTR + ac + 1];
        uint32_t w10 = sSw[(size_t)(g+8) * SSTR + ac],     w11 = sSw[(size_t)(g+8) * SSTR + ac + 1];
        uint32_t w20 = sSw[(size_t)g * SSTR + ac + 8],     w21 = sSw[(size_t)g * SSTR + ac + 9];
        uint32_t w30 = sSw[(size_t)(g+8) * SSTR + ac + 8], w31 = sSw[(size_t)(g+8) * SSTR + ac + 9];
        uint32_t ah0 = PHI(w00,w01), ah1 = PHI(w10,w11), ah2 = PHI(w20,w21), ah3 = PHI(w30,w31);
        uint32_t al0 = PLO(w00,w01), al1 = PLO(w10,w11), al2 = PLO(w20,w21), al3 = PLO(w30,w31);
        int jb2 = x * 16 + 2 * tig;
        #pragma unroll
        for (int nt = 0; nt < 2; nt++) {
            int dim = q4 * 16 + 8 * nt + g;
            uint32_t v0 = sV[dim * VSTR2 + jb2],     v1 = sV[dim * VSTR2 + jb2 + 1];
            uint32_t v2 = sV[dim * VSTR2 + jb2 + 8], v3 = sV[dim * VSTR2 + jb2 + 9];
            uint32_t bh0 = PHI(v0, v1), bl0 = PLO(v0, v1);
            uint32_t bh1 = PHI(v2, v3), bl1 = PLO(v2, v3);
            MMA(oc[nt], ah0, ah1, ah2, ah3, bh0, bh1);
            MMA(oc[nt], ah0, ah1, ah2, ah3, bl0, bl1);
            MMA(oc[nt], al0, al1, al2, al3, bh0, bh1);
        }
    }
    // cross-window reduce via freed staging region
    __syncthreads();
    {
        float* part = (float*)(smem + OFF_KV);
        #pragma unroll
        for (int nt = 0; nt < 2; nt++) {
            int dimb = q4 * 16 + 8 * nt + 2 * tig;
            *(float2*)(part + x * 1024 + g * 64 + dimb)       = make_float2(oc[nt][0], oc[nt][1]);
            *(float2*)(part + x * 1024 + (g + 8) * 64 + dimb) = make_float2(oc[nt][2], oc[nt][3]);
        }
    }
    __syncthreads();
    {
        const float* part = (const float*)(smem + OFF_KV);
        int row = t >> 6, dim = t & 63;
        float s = 0.f;
        #pragma unroll
        for (int xx = 0; xx < 8; xx++) s += part[xx * 1024 + row * 64 + dim];
        O[((size_t)bh * LSEQ + i0 + row) * 64 + dim] = s;
    }
}

extern "C" void kernel_launch(void* const* d_in, const int* in_sizes, int n_in,
                              void* d_out, int out_size)
{
    const float* Q  = (const float*)d_in[0];
    const float* K  = (const float*)d_in[1];
    const float* V  = (const float*)d_in[2];
    const unsigned char* M = (const unsigned char*)d_in[3];
    const float* TS = (const float*)d_in[4];
    const float* LS = (const float*)d_in[5];
    float* out = (float*)d_out;
    float* O = out;
    float* P = out + (size_t)NBH * LSEQ * 64;

    prep_kernel<<<1536, 256>>>(Q, K, V);
    cudaFuncSetAttribute(raa_kernel, cudaFuncAttributeMaxDynamicSharedMemorySize, SMEM_BYTES);
    dim3 grid(LSEQ / 16, NBH);
    raa_kernel<<<grid, NT, SMEM_BYTES>>>(M, TS, LS, O, P);
}

// round 12
// speedup vs baseline: 1.2559x; 1.0026x over previous
#include <cuda_runtime.h>
#include <cuda_bf16.h>
#include <cstdint>

#define LSEQ 2048
#define NBH  16
#define NT   1024
#define SCALE 0.07216878364870323f   // 1/sqrt(3*64)
#define SSTR 2052
#define KSTR 68
#define VSTR2 132
#define PSTR 132

#define OFF_KV 131328                // sS = 16*2052*4
#define KBUF   34816                 // 128*68*4
#define VBUF   33792                 // 64*132*4
#define OFF_Q  200960                // OFF_KV + 2*KBUF
#define OFF_P2 205312                // OFF_Q + 4352
#define SMEM_BYTES 213760            // OFF_P2 + 16*132*4 (8448)

__device__ uint32_t g_qp[(size_t)NBH * LSEQ * 64];
__device__ uint32_t g_kp[(size_t)NBH * LSEQ * 64];
__device__ uint32_t g_vp[(size_t)NBH * 64 * LSEQ];   // [bh][dim][j]

__device__ __forceinline__ uint32_t packsplit(float x) {
    __nv_bfloat16 h = __float2bfloat16(x);
    float hf = __bfloat162float(h);
    __nv_bfloat16 l = __float2bfloat16(x - hf);
    unsigned short hs = *(unsigned short*)&h, ls = *(unsigned short*)&l;
    return (uint32_t)hs | ((uint32_t)ls << 16);
}
__device__ __forceinline__ uint32_t smem_u32(const void* p) {
    uint32_t a;
    asm("{ .reg .u64 t; cvta.to.shared.u64 t, %1; cvt.u32.u64 %0, t; }" : "=r"(a) : "l"(p));
    return a;
}
#define PHI(w0,w1) __byte_perm((w0), (w1), 0x5410)
#define PLO(w0,w1) __byte_perm((w0), (w1), 0x7632)
#define MMA(c, a0,a1,a2,a3, b0,b1) \
  asm volatile("mma.sync.aligned.m16n8k16.row.col.f32.bf16.bf16.f32 " \
    "{%0,%1,%2,%3}, {%4,%5,%6,%7}, {%8,%9}, {%0,%1,%2,%3};" \
    : "+f"((c)[0]), "+f"((c)[1]), "+f"((c)[2]), "+f"((c)[3]) \
    : "r"(a0), "r"(a1), "r"(a2), "r"(a3), "r"(b0), "r"(b1))
#define CPA(dst, src) asm volatile("cp.async.cg.shared.global [%0], [%1], 16;" :: "r"(dst), "l"(src))
#define CPCOMMIT()    asm volatile("cp.async.commit_group;" ::: "memory")
#define CPWAIT0()     asm volatile("cp.async.wait_group 0;" ::: "memory")

// ---------------- prep: pack Q/K; transpose+pack V ----------------
__global__ void prep_kernel(const float* __restrict__ Q, const float* __restrict__ K,
                            const float* __restrict__ V)
{
    const int t = threadIdx.x;
    if (blockIdx.x < 1024) {
        #pragma unroll
        for (int i = 0; i < 2; i++) {
            size_t idx4 = (size_t)blockIdx.x * 512 + t + (size_t)i * 256;
            float4 q = ((const float4*)Q)[idx4];
            ((uint4*)g_qp)[idx4] = make_uint4(packsplit(q.x), packsplit(q.y),
                                             packsplit(q.z), packsplit(q.w));
            float4 k = ((const float4*)K)[idx4];
            ((uint4*)g_kp)[idx4] = make_uint4(packsplit(k.x), packsplit(k.y),
                                             packsplit(k.z), packsplit(k.w));
        }
    } else {
        __shared__ float sT[64 * 65];
        int bi = blockIdx.x - 1024, bh = bi >> 5, jt = bi & 31;
        const float* Vb = V + ((size_t)bh * LSEQ + jt * 64) * 64;
        #pragma unroll
        for (int i = 0; i < 4; i++) {
            int q = t + i * 256, j = q >> 4, n4 = (q & 15) * 4;
            float4 v = *(const float4*)(Vb + (size_t)j * 64 + n4);
            sT[(n4+0)*65 + j] = v.x; sT[(n4+1)*65 + j] = v.y;
            sT[(n4+2)*65 + j] = v.z; sT[(n4+3)*65 + j] = v.w;
        }
        __syncthreads();
        #pragma unroll
        for (int i = 0; i < 4; i++) {
            int q = t + i * 256, dim = q >> 4, j4 = (q & 15) * 4;
            uint4 pw = make_uint4(packsplit(sT[dim*65 + j4]),
                                  packsplit(sT[dim*65 + j4 + 1]),
                                  packsplit(sT[dim*65 + j4 + 2]),
                                  packsplit(sT[dim*65 + j4 + 3]));
            *(uint4*)(g_vp + ((size_t)bh * 64 + dim) * LSEQ + jt * 64 + j4) = pw;
        }
    }
}

__device__ __forceinline__ unsigned mget2(const unsigned char* M, int flag, size_t off)
{
    if (flag == 1) { int2 v = *(const int2*)((const int*)M + off);
        return (v.x?1u:0u) | (v.y?2u:0u); }
    if (flag == 0) { const unsigned char* p = M + off;
        return (p[0]?1u:0u) | (p[1]?2u:0u); }
    float2 v = *(const float2*)((const float*)M + off);
    return (v.x!=0.f?1u:0u) | (v.y!=0.f?2u:0u);
}

// ---------------- main fused kernel: 1024 threads ----------------
__global__ __launch_bounds__(NT, 1)
void raa_kernel(const unsigned char* __restrict__ M,
                const float* __restrict__ TS, const float* __restrict__ LS,
                float* __restrict__ O, float* __restrict__ P)
{
    extern __shared__ char smem[];
    float*    sS  = (float*)smem;
    uint32_t* sSw = (uint32_t*)smem;
    uint32_t* sQ  = (uint32_t*)(smem + OFF_Q);
    float*    sP2 = (float*)(smem + OFF_P2);
    __shared__ float sRow[16];
    __shared__ float sPart[32];
    __shared__ int   sFlag;

    const int t = threadIdx.x, w = t >> 5, lane = t & 31;
    const int g = lane >> 2, tig = lane & 3;
    const int bh = blockIdx.y, i0 = blockIdx.x * 16;

    if (t == 0) {
        const int* mi = (const int*)M; const float* mf = (const float*)M;
        bool okI = true, okF = true;
        for (int i = 0; i < 64; i++) {
            int vi = mi[i]; float vf = mf[i];
            if (vi != 0 && vi != 1)     okI = false;
            if (vf != 0.f && vf != 1.f) okF = false;
        }
        sFlag = okI ? 1 : (okF ? 2 : 0);
    }
    if (t < 256) {
        int row = t >> 4, k4 = (t & 15) * 4;
        uint4 pw = *((const uint4*)(g_qp + ((size_t)bh * LSEQ + i0) * 64) + t);
        *(uint4*)(sQ + row * KSTR + k4) = pw;
    }
    __syncthreads();
    const int flag = sFlag;

    // ---- Phase 1: S = exp((QK^T+bias)*scale); k-split MMA + fused epilogue ----
    const int nt1 = w & 15, kh = w >> 4;
    uint32_t qh[8], ql[8];
    #pragma unroll
    for (int kkl = 0; kkl < 2; kkl++) {
        int ks = kh * 2 + kkl;
        int c0 = ks * 16 + 2 * tig;
        uint2 a0 = *(const uint2*)(sQ + g * KSTR + c0);
        uint2 a1 = *(const uint2*)(sQ + (g + 8) * KSTR + c0);
        uint2 a2 = *(const uint2*)(sQ + g * KSTR + c0 + 8);
        uint2 a3 = *(const uint2*)(sQ + (g + 8) * KSTR + c0 + 8);
        qh[kkl*4+0] = PHI(a0.x, a0.y); ql[kkl*4+0] = PLO(a0.x, a0.y);
        qh[kkl*4+1] = PHI(a1.x, a1.y); ql[kkl*4+1] = PLO(a1.x, a1.y);
        qh[kkl*4+2] = PHI(a2.x, a2.y); ql[kkl*4+2] = PLO(a2.x, a2.y);
        qh[kkl*4+3] = PHI(a3.x, a3.y); ql[kkl*4+3] = PLO(a3.x, a3.y);
    }

    // epilogue mapping: warp -> (row, 64-col half); lane -> 2 cols
    const int erow = w >> 1, ecol0 = (w & 1) * 64 + lane * 2;
    const size_t egrow = (size_t)bh * LSEQ + i0 + erow;
    const float* tsr = TS + egrow * LSEQ;
    const float* lsr = LS + egrow * LSEQ;
    const size_t mrow = ((size_t)(bh >> 3) * LSEQ + i0 + erow) * LSEQ;
    float rsum = 0.f;

    const uint4* Kp = (const uint4*)(g_kp + (size_t)bh * LSEQ * 64);
    const uint32_t kbuf0 = smem_u32(smem + OFF_KV);
    {
        #pragma unroll
        for (int i = 0; i < 2; i++) {
            int idx = t + i * NT, j = idx >> 4, k4 = idx & 15;
            CPA(kbuf0 + (uint32_t)((j * KSTR + k4 * 4) * 4), (const void*)(Kp + j * 16 + k4));
        }
        CPCOMMIT();
    }
    for (int c = 0; c < 16; c++) {
        CPWAIT0();
        __syncthreads();
        if (c + 1 < 16) {
            uint32_t db = kbuf0 + ((c + 1) & 1) * KBUF;
            const uint4* src = Kp + (size_t)(c + 1) * 128 * 16;
            #pragma unroll
            for (int i = 0; i < 2; i++) {
                int idx = t + i * NT, j = idx >> 4, k4 = idx & 15;
                CPA(db + (uint32_t)((j * KSTR + k4 * 4) * 4), (const void*)(src + j * 16 + k4));
            }
            CPCOMMIT();
        }
        // bias/mask prefetch for this chunk (latency hidden behind MMAs)
        const int gcol = c * 128 + ecol0;
        float2 t2 = *(const float2*)(tsr + gcol);
        float2 l2 = *(const float2*)(lsr + gcol);
        unsigned mb = mget2(M, flag, mrow + gcol);

        const uint32_t* sK = (const uint32_t*)(smem + OFF_KV + (c & 1) * KBUF);
        float acc[4] = {0.f, 0.f, 0.f, 0.f};
        const int jrow = nt1 * 8 + g;
        #pragma unroll
        for (int kkl = 0; kkl < 2; kkl++) {
            int kw = (kh * 2 + kkl) * 16 + 2 * tig;
            uint2 b01 = *(const uint2*)(sK + jrow * KSTR + kw);
            uint2 b23 = *(const uint2*)(sK + jrow * KSTR + kw + 8);
            uint32_t b0 = PHI(b01.x, b01.y), l0 = PLO(b01.x, b01.y);
            uint32_t b1 = PHI(b23.x, b23.y), l1 = PLO(b23.x, b23.y);
            MMA(acc, qh[kkl*4], qh[kkl*4+1], qh[kkl*4+2], qh[kkl*4+3], b0, b1);
            MMA(acc, qh[kkl*4], qh[kkl*4+1], qh[kkl*4+2], qh[kkl*4+3], l0, l1);
            MMA(acc, ql[kkl*4], ql[kkl*4+1], ql[kkl*4+2], ql[kkl*4+3], b0, b1);
        }
        const int lcol = nt1 * 8 + 2 * tig;
        if (kh == 1) {
            const int col = c * 128 + lcol;
            *(float2*)(sS + (size_t)g * SSTR + col)       = make_float2(acc[0], acc[1]);
            *(float2*)(sS + (size_t)(g + 8) * SSTR + col) = make_float2(acc[2], acc[3]);
        } else {
            *(float2*)(sP2 + g * PSTR + lcol)       = make_float2(acc[0], acc[1]);
            *(float2*)(sP2 + (g + 8) * PSTR + lcol) = make_float2(acc[2], acc[3]);
        }
        __syncthreads();
        // fused epilogue: combine partials + bias + mask + exp
        {
            float* sSr = sS + (size_t)erow * SSTR + gcol;
            float2 sv = *(const float2*)sSr;
            float2 pv = *(const float2*)(sP2 + erow * PSTR + ecol0);
            float e0 = (mb & 1u) ? 0.f : __expf((sv.x + pv.x + t2.x + l2.x) * SCALE);
            float e1 = (mb & 2u) ? 0.f : __expf((sv.y + pv.y + t2.y + l2.y) * SCALE);
            *(float2*)sSr = make_float2(e0, e1);
            rsum += e0 + e1;
        }
    }
    // row sums
    #pragma unroll
    for (int k = 16; k >= 1; k >>= 1)
        rsum += __shfl_xor_sync(0xffffffffu, rsum, k);
    if (lane == 0) sPart[w] = rsum;
    __syncthreads();
    if (t < 16) sRow[t] = 1.0f / (sPart[2 * t] + sPart[2 * t + 1]);
    __syncthreads();

    // ---- Phase 3: normalize, write P, repack packed bf16 in place ----
    {
        float* Pb = P + ((size_t)bh * LSEQ + i0) * LSEQ;
        #pragma unroll
        for (int it = 0; it < 8; it++) {
            int task = t + it * NT;
            int r = task >> 9, c4 = task & 511;
            float rinv = sRow[r];
            float4 e = ((const float4*)(sS + (size_t)r * SSTR))[c4];
            e.x *= rinv; e.y *= rinv; e.z *= rinv; e.w *= rinv;
            *(float4*)(Pb + (size_t)r * LSEQ + c4 * 4) = e;
            uint4 pw = make_uint4(packsplit(e.x), packsplit(e.y), packsplit(e.z), packsplit(e.w));
            ((uint4*)(sSw + (size_t)r * SSTR))[c4] = pw;
        }
    }

    // ---- Phase 4: O = P V; warp = (j-window, dim-quarter) ----
    const uint4* Vp = (const uint4*)(g_vp + (size_t)bh * 64 * LSEQ);
    const int x = w & 7, q4 = w >> 3;
    float oc[2][4];
    #pragma unroll
    for (int nt = 0; nt < 2; nt++)
        oc[nt][0] = oc[nt][1] = oc[nt][2] = oc[nt][3] = 0.f;
    {
        #pragma unroll
        for (int i = 0; i < 2; i++) {
            int idx = t + i * NT, dim = idx >> 5, u4 = idx & 31;
            CPA(kbuf0 + (uint32_t)((dim * VSTR2 + u4 * 4) * 4),
                (const void*)(Vp + (size_t)dim * 512 + u4));
        }
        CPCOMMIT();
    }
    for (int c = 0; c < 16; c++) {
        CPWAIT0();
        __syncthreads();
        if (c + 1 < 16) {
            uint32_t db = kbuf0 + ((c + 1) & 1) * VBUF;
            #pragma unroll
            for (int i = 0; i < 2; i++) {
                int idx = t + i * NT, dim = idx >> 5, u4 = idx & 31;
                CPA(db + (uint32_t)((dim * VSTR2 + u4 * 4) * 4),
                    (const void*)(Vp + (size_t)dim * 512 + (c + 1) * 32 + u4));
            }
            CPCOMMIT();
        }
        const uint32_t* sV = (const uint32_t*)(smem + OFF_KV + (c & 1) * VBUF);
        int ac = c * 128 + x * 16 + 2 * tig;
        uint2 a0 = *(const uint2*)(sSw + (size_t)g * SSTR + ac);
        uint2 a1 = *(const uint2*)(sSw + (size_t)(g + 8) * SSTR + ac);
        uint2 a2 = *(const uint2*)(sSw + (size_t)g * SSTR + ac + 8);
        uint2 a3 = *(const uint2*)(sSw + (size_t)(g + 8) * SSTR + ac + 8);
        uint32_t ah0 = PHI(a0.x, a0.y), ah1 = PHI(a1.x, a1.y);
        uint32_t ah2 = PHI(a2.x, a2.y), ah3 = PHI(a3.x, a3.y);
        uint32_t al0 = PLO(a0.x, a0.y), al1 = PLO(a1.x, a1.y);
        uint32_t al2 = PLO(a2.x, a2.y), al3 = PLO(a3.x, a3.y);
        int jb2 = x * 16 + 2 * tig;
        #pragma unroll
        for (int nt = 0; nt < 2; nt++) {
            int dim = q4 * 16 + 8 * nt + g;
            uint2 b01 = *(const uint2*)(sV + dim * VSTR2 + jb2);
            uint2 b23 = *(const uint2*)(sV + dim * VSTR2 + jb2 + 8);
            uint32_t bh0 = PHI(b01.x, b01.y), bl0 = PLO(b01.x, b01.y);
            uint32_t bh1 = PHI(b23.x, b23.y), bl1 = PLO(b23.x, b23.y);
            MMA(oc[nt], ah0, ah1, ah2, ah3, bh0, bh1);
            MMA(oc[nt], ah0, ah1, ah2, ah3, bl0, bl1);
            MMA(oc[nt], al0, al1, al2, al3, bh0, bh1);
        }
    }
    // cross-window reduce via freed staging region
    __syncthreads();
    {
        float* part = (float*)(smem + OFF_KV);
        #pragma unroll
        for (int nt = 0; nt < 2; nt++) {
            int dimb = q4 * 16 + 8 * nt + 2 * tig;
            *(float2*)(part + x * 1024 + g * 64 + dimb)       = make_float2(oc[nt][0], oc[nt][1]);
            *(float2*)(part + x * 1024 + (g + 8) * 64 + dimb) = make_float2(oc[nt][2], oc[nt][3]);
        }
    }
    __syncthreads();
    {
        const float* part = (const float*)(smem + OFF_KV);
        int row = t >> 6, dim = t & 63;
        float s = 0.f;
        #pragma unroll
        for (int xx = 0; xx < 8; xx++) s += part[xx * 1024 + row * 64 + dim];
        O[((size_t)bh * LSEQ + i0 + row) * 64 + dim] = s;
    }
}

extern "C" void kernel_launch(void* const* d_in, const int* in_sizes, int n_in,
                              void* d_out, int out_size)
{
    const float* Q  = (const float*)d_in[0];
    const float* K  = (const float*)d_in[1];
    const float* V  = (const float*)d_in[2];
    const unsigned char* M = (const unsigned char*)d_in[3];
    const float* TS = (const float*)d_in[4];
    const float* LS = (const float*)d_in[5];
    float* out = (float*)d_out;
    float* O = out;
    float* P = out + (size_t)NBH * LSEQ * 64;

    prep_kernel<<<1536, 256>>>(Q, K, V);
    cudaFuncSetAttribute(raa_kernel, cudaFuncAttributeMaxDynamicSharedMemorySize, SMEM_BYTES);
    dim3 grid(LSEQ / 16, NBH);
    raa_kernel<<<grid, NT, SMEM_BYTES>>>(M, TS, LS, O, P);
}